// round 5
// baseline (speedup 1.0000x reference)
#include <cuda_runtime.h>
#include <math.h>
#include <stdint.h>

// Problem constants (shapes fixed by the dataset)
#define B_    4
#define S0    12          // token_init side; compact row count per batch = 144
#define M144  144         // unique rows per batch
#define MT    576         // B_*M144
#define DIM   256
#define NP    128         // nPnt
#define HID   512         // 4*nPnt
#define H_    120
#define W_    160

typedef unsigned long long ull;

// ---------------- scratch (device globals) ------------------------------------
__device__ float g_A0  [MT * NP];              // compact t @ P^T / 16   [576,128]
__device__ float g_H   [MT * 2 * HID];         // hidden, nr [0,512) na [512,1024)
__device__ float g_adj [MT * NP];              // node_adj  [576,128]
__device__ float g_attn[MT * NP];              // softmaxed attention [576,128]
__device__ float g_nod [B_ * 24 * NP * DIM];   // compact token_n [4,24,128,256]
__device__ float g_fus [B_ * NP * DIM];        // token_fused [4,128,256]
__device__ float g_U   [MT * DIM];             // unique output rows [576,256]

__device__ __forceinline__ float gelu_exact(float x) {
    return 0.5f * x * (1.0f + erff(x * 0.70710678118654752440f));
}
__device__ __forceinline__ ull pack2(float x, float y) {
    ull r; asm("mov.b64 %0, {%1, %2};" : "=l"(r) : "f"(x), "f"(y)); return r;
}
__device__ __forceinline__ void unpack2(ull v, float& x, float& y) {
    asm("mov.b64 {%0, %1}, %2;" : "=f"(x), "=f"(y) : "l"(v));
}
__device__ __forceinline__ ull fma2(ull a, ull b, ull c) {
    ull d; asm("fma.rn.f32x2 %0, %1, %2, %3;" : "=l"(d) : "l"(a), "l"(b), "l"(c));
    return d;
}

// ===================== templated fp32 GEMM ====================================
// C = act( alpha * A @ B(^T) + bias ) + R ; optional fused row softmax (SMAX)
// DUAL: blockIdx.z = bz*2+br; br selects B0/B1, bias0/bias1, C0/C1, ofsA/ofsC.
// SMAX requires TM==1 and BN/TN==32 (one warp per output row); applied on the
// br==1 branch (or always when !DUAL).
template<int BM, int BN, int BK, int TM, int TN,
         bool TRANSB, bool ACT, bool BIAS, bool RESID, bool DUAL, bool SMAX>
__global__ __launch_bounds__((BM / TM) * (BN / TN))
void gemm_f32(const float* __restrict__ A,
              const float* __restrict__ B0, const float* __restrict__ B1,
              const float* __restrict__ bias0, const float* __restrict__ bias1,
              const float* __restrict__ R,
              float* __restrict__ C0, float* __restrict__ C1,
              int K, float alpha,
              long sA, int lda, int ofsA,
              long sB, int ldb,
              long sC, int ldc, int ofsC,
              long sR, int ldr)
{
    constexpr int THREADS = (BM / TM) * (BN / TN);
    constexpr int NA = (BM * BK) / THREADS;     // A elems per thread per tile
    constexpr int NB = (BN * BK) / THREADS;     // B elems per thread per tile
    static_assert(NA * THREADS == BM * BK, "A load divisibility");
    static_assert(NB * THREADS == BN * BK, "B load divisibility");
    static_assert(!SMAX || (TM == 1 && (BN / TN) == 32), "SMAX layout");

    const int z  = blockIdx.z;
    const int bz = DUAL ? (z >> 1) : z;
    const int br = DUAL ? (z & 1) : 0;

    const float* Bw  = (DUAL && br) ? B1 : B0;
    const float* bia = (DUAL && br) ? bias1 : bias0;
    float*       C   = (DUAL && br) ? C1 : C0;

    A  += (long)bz * sA + (long)br * ofsA;
    Bw += (long)bz * sB;
    C  += (long)bz * sC + (long)br * ofsC;
    const float* Rp = R + (long)bz * sR;

    __shared__ float As[BK][BM + 1];
    __shared__ float Bs[BK][BN + 1];

    const int tid  = threadIdx.x;
    const int row0 = blockIdx.y * BM;
    const int col0 = blockIdx.x * BN;
    const int tn   = tid % (BN / TN);
    const int tm   = tid / (BN / TN);
    const int m0   = tm * TM;
    const int n0   = tn * TN;

    float acc[TM][TN];
#pragma unroll
    for (int i = 0; i < TM; i++)
#pragma unroll
        for (int j = 0; j < TN; j++) acc[i][j] = 0.f;

    float regA[NA], regB[NB];
    const int nT = K / BK;

    // prologue: load tile 0 into regs
#pragma unroll
    for (int j = 0; j < NA; j++) {
        int idx = tid + j * THREADS;
        int r = idx / BK, k = idx % BK;
        regA[j] = A[(long)(row0 + r) * lda + k];
    }
#pragma unroll
    for (int j = 0; j < NB; j++) {
        int idx = tid + j * THREADS;
        if (TRANSB) { int n = idx / BK, k = idx % BK; regB[j] = Bw[(long)(col0 + n) * ldb + k]; }
        else        { int k = idx / BN, n = idx % BN; regB[j] = Bw[(long)k * ldb + col0 + n]; }
    }

    for (int t = 0; t < nT; t++) {
        // regs -> smem
#pragma unroll
        for (int j = 0; j < NA; j++) {
            int idx = tid + j * THREADS;
            int r = idx / BK, k = idx % BK;
            As[k][r] = regA[j];
        }
#pragma unroll
        for (int j = 0; j < NB; j++) {
            int idx = tid + j * THREADS;
            if (TRANSB) { int n = idx / BK, k = idx % BK; Bs[k][n] = regB[j]; }
            else        { int k = idx / BN, n = idx % BN; Bs[k][n] = regB[j]; }
        }
        __syncthreads();

        // prefetch next tile
        if (t + 1 < nT) {
            const int k0 = (t + 1) * BK;
#pragma unroll
            for (int j = 0; j < NA; j++) {
                int idx = tid + j * THREADS;
                int r = idx / BK, k = idx % BK;
                regA[j] = A[(long)(row0 + r) * lda + k0 + k];
            }
#pragma unroll
            for (int j = 0; j < NB; j++) {
                int idx = tid + j * THREADS;
                if (TRANSB) { int n = idx / BK, k = idx % BK; regB[j] = Bw[(long)(col0 + n) * ldb + k0 + k]; }
                else        { int k = idx / BN, n = idx % BN; regB[j] = Bw[(long)(k0 + k) * ldb + col0 + n]; }
            }
        }

        // compute
#pragma unroll
        for (int kk = 0; kk < BK; kk++) {
            float av[TM], bv[TN];
#pragma unroll
            for (int i = 0; i < TM; i++) av[i] = As[kk][m0 + i];
#pragma unroll
            for (int j = 0; j < TN; j++) bv[j] = Bs[kk][n0 + j];
#pragma unroll
            for (int i = 0; i < TM; i++)
#pragma unroll
                for (int j = 0; j < TN; j++)
                    acc[i][j] += av[i] * bv[j];
        }
        __syncthreads();
    }

    // epilogue
    float bf[TN];
#pragma unroll
    for (int j = 0; j < TN; j++) bf[j] = BIAS ? bia[col0 + n0 + j] : 0.f;
#pragma unroll
    for (int i = 0; i < TM; i++) {
        const int row = row0 + m0 + i;
        float v[TN];
#pragma unroll
        for (int j = 0; j < TN; j++) {
            v[j] = acc[i][j] * alpha + bf[j];
            if (ACT)   v[j] = gelu_exact(v[j]);
            if (RESID) v[j] += Rp[(long)row * ldr + col0 + n0 + j];
        }
        if (SMAX && (!DUAL || br)) {
            float mx = v[0];
#pragma unroll
            for (int j = 1; j < TN; j++) mx = fmaxf(mx, v[j]);
#pragma unroll
            for (int o = 16; o; o >>= 1) mx = fmaxf(mx, __shfl_xor_sync(0xffffffffu, mx, o));
            float sum = 0.f;
#pragma unroll
            for (int j = 0; j < TN; j++) { v[j] = expf(v[j] - mx); sum += v[j]; }
#pragma unroll
            for (int o = 16; o; o >>= 1) sum += __shfl_xor_sync(0xffffffffu, sum, o);
            float inv = 1.f / sum;
#pragma unroll
            for (int j = 0; j < TN; j++) v[j] *= inv;
        }
#pragma unroll
        for (int j = 0; j < TN; j++)
            C[(long)row * ldc + col0 + n0 + j] = v[j];
    }
}

// ---------------- node_w / node_h on the compact 12x12 grid (p-split) ---------
// blockIdx.x=fix(12), blockIdx.y=b(4), blockIdx.z = mode*4 + psplit(4)
// mode 0: srow=h'    : 2*rs * sum_{w'} adj[h',w',p] * t[h',w',d]
// mode 1: srow=12+w' : 2*rs * sum_{h'} adj[h',w',p] * t[h',w',d]
__global__ __launch_bounds__(256)
void node_wh_kernel(const float* __restrict__ token_init, float rs2) {
    __shared__ __align__(16) float adj_s[S0][32];     // 1.5 KB
    __shared__ __align__(16) float t_s  [S0][DIM];    // 12 KB
    const int fix  = blockIdx.x;
    const int b    = blockIdx.y;
    const int mode = blockIdx.z >> 2;
    const int p0   = (blockIdx.z & 3) * 32;
    const int tid  = threadIdx.x;

    if (tid < S0 * 32) {
        int m = tid >> 5, p = tid & 31;
        int r = mode ? (m * S0 + fix) : (fix * S0 + m);
        adj_s[m][p] = g_adj[(b * M144 + r) * NP + p0 + p];
    }
    for (int idx = tid; idx < S0 * DIM; idx += 256) {
        int m = idx >> 8, d = idx & 255;
        int r = mode ? (m * S0 + fix) : (fix * S0 + m);
        t_s[m][d] = token_init[((long)b * M144 + r) * DIM + d];
    }
    __syncthreads();

    const int d = tid;
    const int srow = mode ? (S0 + fix) : fix;
#pragma unroll
    for (int pb = 0; pb < 2; pb++) {
        ull acc2[8];
#pragma unroll
        for (int i = 0; i < 8; i++) acc2[i] = pack2(0.f, 0.f);
#pragma unroll
        for (int m = 0; m < S0; m++) {
            float tv = t_s[m][d];
            ull tv2 = pack2(tv, tv);
            const ull* ap = (const ull*)&adj_s[m][pb * 16];
#pragma unroll
            for (int i = 0; i < 8; i++)
                acc2[i] = fma2(ap[i], tv2, acc2[i]);
        }
#pragma unroll
        for (int i = 0; i < 8; i++) {
            float x, y; unpack2(acc2[i], x, y);
            const int p = p0 + pb * 16 + 2 * i;
            g_nod[((long)(b * 24 + srow) * NP + p + 0) * DIM + d] = x * rs2;
            g_nod[((long)(b * 24 + srow) * NP + p + 1) * DIM + d] = y * rs2;
        }
    }
}

// ---------------- token_fused MLP, folded 48->24 axis, 1 d per thread ---------
__global__ __launch_bounds__(256)
void token_fused_kernel(const float* __restrict__ w1, const float* __restrict__ b1,
                        const float* __restrict__ w2, const float* __restrict__ b2) {
    __shared__ float w1t[48][24];   // folded+transposed: w1t[j][i] = w1[2i][j]+w1[2i+1][j]
    __shared__ float b1s[48];
    __shared__ float w2s[48];
    const int tid = threadIdx.x;
    for (int idx = tid; idx < 48 * 24; idx += 256) {
        int j = idx / 24, i = idx % 24;
        w1t[j][i] = w1[(2 * i) * 48 + j] + w1[(2 * i + 1) * 48 + j];
    }
    if (tid < 48) { b1s[tid] = b1[tid]; w2s[tid] = w2[tid]; }
    __syncthreads();

    const int bp = blockIdx.x;        // 0..511 = b*128+p
    const int b  = bp >> 7;
    const int p  = bp & 127;
    const int d  = tid;

    float x[24];
#pragma unroll
    for (int i = 0; i < 24; i++)
        x[i] = g_nod[((long)(b * 24 + i) * NP + p) * DIM + d];

    float out = b2[0];
    for (int j = 0; j < 48; j++) {
        float a = b1s[j];
        const float4* wr = (const float4*)&w1t[j][0];
#pragma unroll
        for (int i4 = 0; i4 < 6; i4++) {
            float4 wv = wr[i4];
            a += x[i4 * 4 + 0] * wv.x + x[i4 * 4 + 1] * wv.y
               + x[i4 * 4 + 2] * wv.z + x[i4 * 4 + 3] * wv.w;
        }
        out += gelu_exact(a) * w2s[j];
    }
    g_fus[bp * DIM + d] = out;
}

// ---------------- final scatter-broadcast of the 144 unique rows --------------
__global__ __launch_bounds__(256)
void scatter_kernel(float4* __restrict__ out) {
    const int wq = threadIdx.x >> 6;          // 0..3
    const int dq = threadIdx.x & 63;          // 0..63
    const int w  = blockIdx.x * 4 + wq;
    const int h  = blockIdx.y;
    const int b  = blockIdx.z;
    const int r  = (h / 10) * S0 + (3 * w) / 40;
    const float4* src = reinterpret_cast<const float4*>(g_U)
                        + (long)(b * M144 + r) * (DIM / 4);
    float4* dst = out + (long)(((b * H_) + h) * W_ + w) * (DIM / 4);
    dst[dq] = src[dq];
}

// ==============================================================================
extern "C" void kernel_launch(void* const* d_in, const int* in_sizes, int n_in,
                              void* d_out, int out_size) {
    const float* token_init  = (const float*)d_in[0];   // [4,12,12,256] == compact t
    const float* point_token = (const float*)d_in[1];
    const float* nr_w1 = (const float*)d_in[2];
    const float* nr_b1 = (const float*)d_in[3];
    const float* nr_w2 = (const float*)d_in[4];
    const float* nr_b2 = (const float*)d_in[5];
    const float* na_w1 = (const float*)d_in[6];
    const float* na_b1 = (const float*)d_in[7];
    const float* na_w2 = (const float*)d_in[8];
    const float* na_b2 = (const float*)d_in[9];
    const float* tf_w1 = (const float*)d_in[10];
    const float* tf_b1 = (const float*)d_in[11];
    const float* tf_w2 = (const float*)d_in[12];
    const float* tf_b2 = (const float*)d_in[13];
    float* out = (float*)d_out;

    float *A0_p, *H_p, *adj_p, *attn_p, *fus_p, *U_p;
    cudaGetSymbolAddress((void**)&A0_p,   g_A0);
    cudaGetSymbolAddress((void**)&H_p,    g_H);
    cudaGetSymbolAddress((void**)&adj_p,  g_adj);
    cudaGetSymbolAddress((void**)&attn_p, g_attn);
    cudaGetSymbolAddress((void**)&fus_p,  g_fus);
    cudaGetSymbolAddress((void**)&U_p,    g_U);

    const float scale = 0.0625f;                    // dim^-0.5
    const float rs2   = 2.f * 0.20412414523193154f; // 2 * 24^-0.5

    // 1. A0 = t144 @ P^T * scale   [4*144,128]  (t144 == token_init)
    gemm_f32<16, 32, 16, 1, 4, true, false, false, false, false, false>
        <<<dim3(NP / 32, M144 / 16, B_), 128>>>(
        token_init, point_token, nullptr, nullptr, nullptr, nullptr, A0_p, nullptr,
        DIM, scale,
        (long)M144 * DIM, DIM, 0,
        (long)NP * DIM, DIM,
        (long)M144 * NP, NP, 0,
        0, 0);

    // 2. fc1 (nr & na): H = gelu(A0 @ w1 + b1)   [576,1024]
    gemm_f32<32, 64, 16, 2, 4, false, true, true, false, true, false>
        <<<dim3(HID / 64, MT / 32, 2), 256>>>(
        A0_p, nr_w1, na_w1, nr_b1, na_b1, nullptr, H_p, H_p,
        NP, 1.f,
        0, NP, 0,
        0, HID,
        0, 2 * HID, HID,
        0, 0);

    // 3. fc2 (nr & na): adj = H@w2+b2 ; attn = softmax(H@w2+b2)  [576,128] each
    gemm_f32<8, 128, 32, 1, 4, false, false, true, false, true, true>
        <<<dim3(1, MT / 8, 2), 256>>>(
        H_p, nr_w2, na_w2, nr_b2, na_b2, nullptr, adj_p, attn_p,
        HID, 1.f,
        0, 2 * HID, HID,
        0, NP,
        0, NP, 0,
        0, 0);

    // 4. node_w / node_h on 12x12 -> compact token_n [4,24,128,256]
    node_wh_kernel<<<dim3(S0, B_, 8), 256>>>(token_init, rs2);

    // 5. token_fused MLP (folded 24-axis) -> [4,128,256]
    token_fused_kernel<<<dim3(B_ * NP), 256>>>(tf_w1, tf_b1, tf_w2, tf_b2);

    // 6. U = attn @ token_fused + t144   [4*144,256]
    gemm_f32<16, 64, 16, 1, 4, false, false, false, true, false, false>
        <<<dim3(DIM / 64, M144 / 16, B_), 256>>>(
        attn_p, fus_p, nullptr, nullptr, nullptr, token_init, U_p, nullptr,
        NP, 1.f,
        (long)M144 * NP, NP, 0,
        (long)NP * DIM, DIM,
        (long)M144 * DIM, DIM, 0,
        (long)M144 * DIM, DIM);

    // 7. broadcast unique rows to the full [4,19200,256] output
    scatter_kernel<<<dim3(W_ / 4, H_, B_), 256>>>((float4*)out);
}

// round 6
// speedup vs baseline: 1.0857x; 1.0857x over previous
#include <cuda_runtime.h>
#include <math.h>
#include <stdint.h>

// Problem constants (shapes fixed by the dataset)
#define B_    4
#define S0    12          // token_init side; compact row count per batch = 144
#define M144  144         // unique rows per batch
#define MT    576         // B_*M144
#define DIM   256
#define NP    128         // nPnt
#define HID   512         // 4*nPnt
#define H_    120
#define W_    160

typedef unsigned long long ull;

// ---------------- scratch (device globals) ------------------------------------
__device__ float g_A0  [MT * NP];              // compact t @ P^T / 16   [576,128]
__device__ float g_H   [MT * 2 * HID];         // hidden, nr [0,512) na [512,1024)
__device__ float g_adj [MT * NP];              // node_adj  [576,128]
__device__ float g_attn[MT * NP];              // softmax in-place [576,128]
__device__ float g_nod [B_ * 24 * NP * DIM];   // compact token_n [4,24,128,256]
__device__ float g_fus [B_ * NP * DIM];        // token_fused [4,128,256]
__device__ float g_U   [MT * DIM];             // unique output rows [576,256]

__device__ __forceinline__ float gelu_exact(float x) {
    return 0.5f * x * (1.0f + erff(x * 0.70710678118654752440f));
}
__device__ __forceinline__ ull pack2(float x, float y) {
    ull r; asm("mov.b64 %0, {%1, %2};" : "=l"(r) : "f"(x), "f"(y)); return r;
}
__device__ __forceinline__ void unpack2(ull v, float& x, float& y) {
    asm("mov.b64 {%0, %1}, %2;" : "=f"(x), "=f"(y) : "l"(v));
}
__device__ __forceinline__ ull fma2(ull a, ull b, ull c) {
    ull d; asm("fma.rn.f32x2 %0, %1, %2, %3;" : "=l"(d) : "l"(a), "l"(b), "l"(c));
    return d;
}

// ===================== templated fp32 GEMM (R4-proven) ========================
// C = act( alpha * A @ B(^T) + bias ) + R
// DUAL: blockIdx.z = bz*2+br; br selects B0/B1, bias0/bias1, C0/C1, ofsA/ofsC.
template<int BM, int BN, int BK, int TM, int TN,
         bool TRANSB, bool ACT, bool BIAS, bool RESID, bool DUAL>
__global__ __launch_bounds__((BM / TM) * (BN / TN))
void gemm_f32(const float* __restrict__ A,
              const float* __restrict__ B0, const float* __restrict__ B1,
              const float* __restrict__ bias0, const float* __restrict__ bias1,
              const float* __restrict__ R,
              float* __restrict__ C0, float* __restrict__ C1,
              int K, float alpha,
              long sA, int lda, int ofsA,
              long sB, int ldb,
              long sC, int ldc, int ofsC,
              long sR, int ldr)
{
    constexpr int THREADS = (BM / TM) * (BN / TN);
    constexpr int NA = (BM * BK) / THREADS;     // A elems per thread per tile
    constexpr int NB = (BN * BK) / THREADS;     // B elems per thread per tile
    static_assert(NA * THREADS == BM * BK, "A load divisibility");
    static_assert(NB * THREADS == BN * BK, "B load divisibility");

    const int z  = blockIdx.z;
    const int bz = DUAL ? (z >> 1) : z;
    const int br = DUAL ? (z & 1) : 0;

    const float* Bw  = (DUAL && br) ? B1 : B0;
    const float* bia = (DUAL && br) ? bias1 : bias0;
    float*       C   = (DUAL && br) ? C1 : C0;

    A  += (long)bz * sA + (long)br * ofsA;
    Bw += (long)bz * sB;
    C  += (long)bz * sC + (long)br * ofsC;
    const float* Rp = R + (long)bz * sR;

    __shared__ float As[BK][BM + 1];
    __shared__ float Bs[BK][BN + 1];

    const int tid  = threadIdx.x;
    const int row0 = blockIdx.y * BM;
    const int col0 = blockIdx.x * BN;
    const int tn   = tid % (BN / TN);
    const int tm   = tid / (BN / TN);
    const int m0   = tm * TM;
    const int n0   = tn * TN;

    float acc[TM][TN];
#pragma unroll
    for (int i = 0; i < TM; i++)
#pragma unroll
        for (int j = 0; j < TN; j++) acc[i][j] = 0.f;

    float regA[NA], regB[NB];
    const int nT = K / BK;

    // prologue: load tile 0 into regs
#pragma unroll
    for (int j = 0; j < NA; j++) {
        int idx = tid + j * THREADS;
        int r = idx / BK, k = idx % BK;
        regA[j] = A[(long)(row0 + r) * lda + k];
    }
#pragma unroll
    for (int j = 0; j < NB; j++) {
        int idx = tid + j * THREADS;
        if (TRANSB) { int n = idx / BK, k = idx % BK; regB[j] = Bw[(long)(col0 + n) * ldb + k]; }
        else        { int k = idx / BN, n = idx % BN; regB[j] = Bw[(long)k * ldb + col0 + n]; }
    }

    for (int t = 0; t < nT; t++) {
        // regs -> smem
#pragma unroll
        for (int j = 0; j < NA; j++) {
            int idx = tid + j * THREADS;
            int r = idx / BK, k = idx % BK;
            As[k][r] = regA[j];
        }
#pragma unroll
        for (int j = 0; j < NB; j++) {
            int idx = tid + j * THREADS;
            if (TRANSB) { int n = idx / BK, k = idx % BK; Bs[k][n] = regB[j]; }
            else        { int k = idx / BN, n = idx % BN; Bs[k][n] = regB[j]; }
        }
        __syncthreads();

        // prefetch next tile
        if (t + 1 < nT) {
            const int k0 = (t + 1) * BK;
#pragma unroll
            for (int j = 0; j < NA; j++) {
                int idx = tid + j * THREADS;
                int r = idx / BK, k = idx % BK;
                regA[j] = A[(long)(row0 + r) * lda + k0 + k];
            }
#pragma unroll
            for (int j = 0; j < NB; j++) {
                int idx = tid + j * THREADS;
                if (TRANSB) { int n = idx / BK, k = idx % BK; regB[j] = Bw[(long)(col0 + n) * ldb + k0 + k]; }
                else        { int k = idx / BN, n = idx % BN; regB[j] = Bw[(long)(k0 + k) * ldb + col0 + n]; }
            }
        }

        // compute
#pragma unroll
        for (int kk = 0; kk < BK; kk++) {
            float av[TM], bv[TN];
#pragma unroll
            for (int i = 0; i < TM; i++) av[i] = As[kk][m0 + i];
#pragma unroll
            for (int j = 0; j < TN; j++) bv[j] = Bs[kk][n0 + j];
#pragma unroll
            for (int i = 0; i < TM; i++)
#pragma unroll
                for (int j = 0; j < TN; j++)
                    acc[i][j] += av[i] * bv[j];
        }
        __syncthreads();
    }

    // epilogue
    float bf[TN];
#pragma unroll
    for (int j = 0; j < TN; j++) bf[j] = BIAS ? bia[col0 + n0 + j] : 0.f;
#pragma unroll
    for (int i = 0; i < TM; i++) {
        const int row = row0 + m0 + i;
#pragma unroll
        for (int j = 0; j < TN; j++) {
            float v = acc[i][j] * alpha + bf[j];
            if (ACT)   v = gelu_exact(v);
            if (RESID) v += Rp[(long)row * ldr + col0 + n0 + j];
            C[(long)row * ldc + col0 + n0 + j] = v;
        }
    }
}

// ---------------- node_w / node_h on the compact 12x12 grid (p-split x16) -----
// blockIdx.x=fix(12), blockIdx.y=b(4), blockIdx.z = mode*8 + pchunk(8), chunk=16
// mode 0: srow=h'    : 2*rs * sum_{w'} adj[h',w',p] * t[h',w',d]
// mode 1: srow=12+w' : 2*rs * sum_{h'} adj[h',w',p] * t[h',w',d]
__global__ __launch_bounds__(256)
void node_wh_kernel(const float* __restrict__ token_init, float rs2) {
    __shared__ __align__(16) float adj_s[S0][16];     // 768 B
    __shared__ __align__(16) float t_s  [S0][DIM];    // 12 KB
    const int fix  = blockIdx.x;
    const int b    = blockIdx.y;
    const int mode = blockIdx.z >> 3;
    const int p0   = (blockIdx.z & 7) * 16;
    const int tid  = threadIdx.x;

    if (tid < S0 * 16) {
        int m = tid >> 4, p = tid & 15;
        int r = mode ? (m * S0 + fix) : (fix * S0 + m);
        adj_s[m][p] = g_adj[(b * M144 + r) * NP + p0 + p];
    }
    for (int idx = tid; idx < S0 * DIM; idx += 256) {
        int m = idx >> 8, d = idx & 255;
        int r = mode ? (m * S0 + fix) : (fix * S0 + m);
        t_s[m][d] = token_init[((long)b * M144 + r) * DIM + d];
    }
    __syncthreads();

    const int d = tid;
    const int srow = mode ? (S0 + fix) : fix;
    ull acc2[8];
#pragma unroll
    for (int i = 0; i < 8; i++) acc2[i] = pack2(0.f, 0.f);
#pragma unroll
    for (int m = 0; m < S0; m++) {
        float tv = t_s[m][d];
        ull tv2 = pack2(tv, tv);
        const ull* ap = (const ull*)&adj_s[m][0];
#pragma unroll
        for (int i = 0; i < 8; i++)
            acc2[i] = fma2(ap[i], tv2, acc2[i]);
    }
#pragma unroll
    for (int i = 0; i < 8; i++) {
        float x, y; unpack2(acc2[i], x, y);
        const int p = p0 + 2 * i;
        g_nod[((long)(b * 24 + srow) * NP + p + 0) * DIM + d] = x * rs2;
        g_nod[((long)(b * 24 + srow) * NP + p + 1) * DIM + d] = y * rs2;
    }
}

// ---------------- token_fused MLP, folded 48->24 axis, 1 d per thread ---------
__global__ __launch_bounds__(256)
void token_fused_kernel(const float* __restrict__ w1, const float* __restrict__ b1,
                        const float* __restrict__ w2, const float* __restrict__ b2) {
    __shared__ float w1t[48][24];   // folded+transposed: w1t[j][i] = w1[2i][j]+w1[2i+1][j]
    __shared__ float b1s[48];
    __shared__ float w2s[48];
    const int tid = threadIdx.x;
    for (int idx = tid; idx < 48 * 24; idx += 256) {
        int j = idx / 24, i = idx % 24;
        w1t[j][i] = w1[(2 * i) * 48 + j] + w1[(2 * i + 1) * 48 + j];
    }
    if (tid < 48) { b1s[tid] = b1[tid]; w2s[tid] = w2[tid]; }
    __syncthreads();

    const int bp = blockIdx.x;        // 0..511 = b*128+p
    const int b  = bp >> 7;
    const int p  = bp & 127;
    const int d  = tid;

    float x[24];
#pragma unroll
    for (int i = 0; i < 24; i++)
        x[i] = g_nod[((long)(b * 24 + i) * NP + p) * DIM + d];

    float out = b2[0];
    for (int j = 0; j < 48; j++) {
        float a = b1s[j];
        const float4* wr = (const float4*)&w1t[j][0];
#pragma unroll
        for (int i4 = 0; i4 < 6; i4++) {
            float4 wv = wr[i4];
            a += x[i4 * 4 + 0] * wv.x + x[i4 * 4 + 1] * wv.y
               + x[i4 * 4 + 2] * wv.z + x[i4 * 4 + 3] * wv.w;
        }
        out += gelu_exact(a) * w2s[j];
    }
    g_fus[bp * DIM + d] = out;
}

// ---------------- row softmax, N = 128, one block per row ---------------------
__global__ __launch_bounds__(128)
void softmax128_kernel(float* __restrict__ X) {
    const int row = blockIdx.x;
    const int t = threadIdx.x;
    float v = X[row * NP + t];
    __shared__ float red[4];
    float m = v;
#pragma unroll
    for (int o = 16; o; o >>= 1) m = fmaxf(m, __shfl_xor_sync(0xffffffffu, m, o));
    if ((t & 31) == 0) red[t >> 5] = m;
    __syncthreads();
    m = fmaxf(fmaxf(red[0], red[1]), fmaxf(red[2], red[3]));
    float e = expf(v - m);
    __syncthreads();
    float s = e;
#pragma unroll
    for (int o = 16; o; o >>= 1) s += __shfl_xor_sync(0xffffffffu, s, o);
    if ((t & 31) == 0) red[t >> 5] = s;
    __syncthreads();
    s = red[0] + red[1] + red[2] + red[3];
    X[row * NP + t] = e / s;
}

// ---------------- final scatter-broadcast of the 144 unique rows --------------
__global__ __launch_bounds__(256)
void scatter_kernel(float4* __restrict__ out) {
    const int wq = threadIdx.x >> 6;          // 0..3
    const int dq = threadIdx.x & 63;          // 0..63
    const int w  = blockIdx.x * 4 + wq;
    const int h  = blockIdx.y;
    const int b  = blockIdx.z;
    const int r  = (h / 10) * S0 + (3 * w) / 40;
    const float4* src = reinterpret_cast<const float4*>(g_U)
                        + (long)(b * M144 + r) * (DIM / 4);
    float4* dst = out + (long)(((b * H_) + h) * W_ + w) * (DIM / 4);
    dst[dq] = src[dq];
}

// ==============================================================================
extern "C" void kernel_launch(void* const* d_in, const int* in_sizes, int n_in,
                              void* d_out, int out_size) {
    const float* token_init  = (const float*)d_in[0];   // [4,12,12,256] == compact t
    const float* point_token = (const float*)d_in[1];
    const float* nr_w1 = (const float*)d_in[2];
    const float* nr_b1 = (const float*)d_in[3];
    const float* nr_w2 = (const float*)d_in[4];
    const float* nr_b2 = (const float*)d_in[5];
    const float* na_w1 = (const float*)d_in[6];
    const float* na_b1 = (const float*)d_in[7];
    const float* na_w2 = (const float*)d_in[8];
    const float* na_b2 = (const float*)d_in[9];
    const float* tf_w1 = (const float*)d_in[10];
    const float* tf_b1 = (const float*)d_in[11];
    const float* tf_w2 = (const float*)d_in[12];
    const float* tf_b2 = (const float*)d_in[13];
    float* out = (float*)d_out;

    float *A0_p, *H_p, *adj_p, *attn_p, *fus_p, *U_p;
    cudaGetSymbolAddress((void**)&A0_p,   g_A0);
    cudaGetSymbolAddress((void**)&H_p,    g_H);
    cudaGetSymbolAddress((void**)&adj_p,  g_adj);
    cudaGetSymbolAddress((void**)&attn_p, g_attn);
    cudaGetSymbolAddress((void**)&fus_p,  g_fus);
    cudaGetSymbolAddress((void**)&U_p,    g_U);

    const float scale = 0.0625f;                    // dim^-0.5
    const float rs2   = 2.f * 0.20412414523193154f; // 2 * 24^-0.5

    // 1. A0 = t144 @ P^T * scale   [4*144,128]  (t144 == token_init)
    gemm_f32<16, 32, 16, 2, 4, true, false, false, false, false>
        <<<dim3(NP / 32, M144 / 16, B_), 64>>>(
        token_init, point_token, nullptr, nullptr, nullptr, nullptr, A0_p, nullptr,
        DIM, scale,
        (long)M144 * DIM, DIM, 0,
        (long)NP * DIM, DIM,
        (long)M144 * NP, NP, 0,
        0, 0);

    // 2. fc1 (nr & na): H = gelu(A0 @ w1 + b1)   [576,1024]
    gemm_f32<32, 64, 16, 4, 4, false, true, true, false, true>
        <<<dim3(HID / 64, MT / 32, 2), 128>>>(
        A0_p, nr_w1, na_w1, nr_b1, na_b1, nullptr, H_p, H_p,
        NP, 1.f,
        0, NP, 0,
        0, HID,
        0, 2 * HID, HID,
        0, 0);

    // 3. fc2 (nr & na): adj / attn = H @ w2 + b2   [576,128] each
    gemm_f32<32, 32, 16, 4, 2, false, false, true, false, true>
        <<<dim3(NP / 32, MT / 32, 2), 128>>>(
        H_p, nr_w2, na_w2, nr_b2, na_b2, nullptr, adj_p, attn_p,
        HID, 1.f,
        0, 2 * HID, HID,
        0, NP,
        0, NP, 0,
        0, 0);

    // 4. node_w / node_h on 12x12 -> compact token_n [4,24,128,256]
    node_wh_kernel<<<dim3(S0, B_, 16), 256>>>(token_init, rs2);

    // 5. token_fused MLP (folded 24-axis) -> [4,128,256]
    token_fused_kernel<<<dim3(B_ * NP), 256>>>(tf_w1, tf_b1, tf_w2, tf_b2);

    // 6. softmax over the 128 points (576 compact rows)
    softmax128_kernel<<<dim3(MT), 128>>>(attn_p);

    // 7. U = attn @ token_fused + t144   [4*144,256]
    gemm_f32<16, 64, 16, 2, 4, false, false, false, true, false>
        <<<dim3(DIM / 64, M144 / 16, B_), 128>>>(
        attn_p, fus_p, nullptr, nullptr, nullptr, token_init, U_p, nullptr,
        NP, 1.f,
        (long)M144 * NP, NP, 0,
        (long)NP * DIM, DIM,
        (long)M144 * DIM, DIM, 0,
        (long)M144 * DIM, DIM);

    // 8. broadcast unique rows to the full [4,19200,256] output
    scatter_kernel<<<dim3(W_ / 4, H_, B_), 256>>>((float4*)out);
}

// round 7
// speedup vs baseline: 1.3529x; 1.2461x over previous
#include <cuda_runtime.h>
#include <math.h>
#include <stdint.h>

// Problem constants (shapes fixed by the dataset)
#define B_    4
#define S0    12          // token_init side; compact row count per batch = 144
#define M144  144         // unique rows per batch
#define MT    576         // B_*M144
#define DIM   256
#define NP    128         // nPnt
#define HID   512         // 4*nPnt
#define H_    120
#define W_    160

typedef unsigned long long ull;

// ---------------- scratch (device globals) ------------------------------------
__device__ float g_A0   [MT * NP];             // compact t @ P^T / 16   [576,128]
__device__ float g_H    [MT * 2 * HID];        // hidden, nr [0,512) na [512,1024)
__device__ float g_padj [2 * MT * NP];         // fc2 nr partials (split-K halves)
__device__ float g_pattn[2 * MT * NP];         // fc2 na partials
__device__ float g_attn [MT * NP];             // softmaxed attention [576,128]
__device__ float g_fus  [B_ * NP * DIM];       // token_fused [4,128,256]
__device__ float g_U    [MT * DIM];            // unique output rows [576,256]

__device__ __forceinline__ float gelu_exact(float x) {
    return 0.5f * x * (1.0f + erff(x * 0.70710678118654752440f));
}

// ===================== templated fp32 GEMM (R4-proven + split-K) ==============
// C = act( alpha * A @ B(^T) + bias ) + R
// DUAL: z-branch selects B0/B1, bias0/bias1, C0/C1, ofsA/ofsC.
// SPLITK: z also carries k-chunk; partial written at C + kc*sPart (no bias).
template<int BM, int BN, int BK, int TM, int TN,
         bool TRANSB, bool ACT, bool BIAS, bool RESID, bool DUAL, int SPLITK>
__global__ __launch_bounds__((BM / TM) * (BN / TN))
void gemm_f32(const float* __restrict__ A,
              const float* __restrict__ B0, const float* __restrict__ B1,
              const float* __restrict__ bias0, const float* __restrict__ bias1,
              const float* __restrict__ R,
              float* __restrict__ C0, float* __restrict__ C1,
              int K, float alpha,
              long sA, int lda, int ofsA,
              long sB, int ldb,
              long sC, int ldc, int ofsC,
              long sR, int ldr, long sPart)
{
    constexpr int THREADS = (BM / TM) * (BN / TN);
    constexpr int NA = (BM * BK) / THREADS;     // A elems per thread per tile
    constexpr int NB = (BN * BK) / THREADS;     // B elems per thread per tile
    static_assert(NA * THREADS == BM * BK, "A load divisibility");
    static_assert(NB * THREADS == BN * BK, "B load divisibility");

    const int z  = blockIdx.z;
    const int kc = (SPLITK > 1) ? (z % SPLITK) : 0;
    const int r2 = (SPLITK > 1) ? (z / SPLITK) : z;
    const int br = DUAL ? (r2 & 1) : 0;
    const int bz = DUAL ? (r2 >> 1) : r2;

    const int Kc = K / SPLITK;

    const float* Bw  = (DUAL && br) ? B1 : B0;
    const float* bia = (DUAL && br) ? bias1 : bias0;
    float*       C   = (DUAL && br) ? C1 : C0;

    A  += (long)bz * sA + (long)br * ofsA + (long)kc * Kc;
    Bw += (long)bz * sB + (TRANSB ? (long)kc * Kc : (long)kc * Kc * ldb);
    C  += (long)bz * sC + (long)br * ofsC + (long)kc * sPart;
    const float* Rp = R + (long)bz * sR;

    __shared__ float As[BK][BM + 1];
    __shared__ float Bs[BK][BN + 1];

    const int tid  = threadIdx.x;
    const int row0 = blockIdx.y * BM;
    const int col0 = blockIdx.x * BN;
    const int tn   = tid % (BN / TN);
    const int tm   = tid / (BN / TN);
    const int m0   = tm * TM;
    const int n0   = tn * TN;

    float acc[TM][TN];
#pragma unroll
    for (int i = 0; i < TM; i++)
#pragma unroll
        for (int j = 0; j < TN; j++) acc[i][j] = 0.f;

    float regA[NA], regB[NB];
    const int nT = Kc / BK;

    // prologue: load tile 0 into regs
#pragma unroll
    for (int j = 0; j < NA; j++) {
        int idx = tid + j * THREADS;
        int r = idx / BK, k = idx % BK;
        regA[j] = A[(long)(row0 + r) * lda + k];
    }
#pragma unroll
    for (int j = 0; j < NB; j++) {
        int idx = tid + j * THREADS;
        if (TRANSB) { int n = idx / BK, k = idx % BK; regB[j] = Bw[(long)(col0 + n) * ldb + k]; }
        else        { int k = idx / BN, n = idx % BN; regB[j] = Bw[(long)k * ldb + col0 + n]; }
    }

    for (int t = 0; t < nT; t++) {
        // regs -> smem
#pragma unroll
        for (int j = 0; j < NA; j++) {
            int idx = tid + j * THREADS;
            int r = idx / BK, k = idx % BK;
            As[k][r] = regA[j];
        }
#pragma unroll
        for (int j = 0; j < NB; j++) {
            int idx = tid + j * THREADS;
            if (TRANSB) { int n = idx / BK, k = idx % BK; Bs[k][n] = regB[j]; }
            else        { int k = idx / BN, n = idx % BN; Bs[k][n] = regB[j]; }
        }
        __syncthreads();

        // prefetch next tile
        if (t + 1 < nT) {
            const int k0 = (t + 1) * BK;
#pragma unroll
            for (int j = 0; j < NA; j++) {
                int idx = tid + j * THREADS;
                int r = idx / BK, k = idx % BK;
                regA[j] = A[(long)(row0 + r) * lda + k0 + k];
            }
#pragma unroll
            for (int j = 0; j < NB; j++) {
                int idx = tid + j * THREADS;
                if (TRANSB) { int n = idx / BK, k = idx % BK; regB[j] = Bw[(long)(col0 + n) * ldb + k0 + k]; }
                else        { int k = idx / BN, n = idx % BN; regB[j] = Bw[(long)(k0 + k) * ldb + col0 + n]; }
            }
        }

        // compute
#pragma unroll
        for (int kk = 0; kk < BK; kk++) {
            float av[TM], bv[TN];
#pragma unroll
            for (int i = 0; i < TM; i++) av[i] = As[kk][m0 + i];
#pragma unroll
            for (int j = 0; j < TN; j++) bv[j] = Bs[kk][n0 + j];
#pragma unroll
            for (int i = 0; i < TM; i++)
#pragma unroll
                for (int j = 0; j < TN; j++)
                    acc[i][j] += av[i] * bv[j];
        }
        __syncthreads();
    }

    // epilogue
    float bf[TN];
#pragma unroll
    for (int j = 0; j < TN; j++) bf[j] = BIAS ? bia[col0 + n0 + j] : 0.f;
#pragma unroll
    for (int i = 0; i < TM; i++) {
        const int row = row0 + m0 + i;
#pragma unroll
        for (int j = 0; j < TN; j++) {
            float v = acc[i][j] * alpha + bf[j];
            if (ACT)   v = gelu_exact(v);
            if (RESID) v += Rp[(long)row * ldr + col0 + n0 + j];
            C[(long)row * ldc + col0 + n0 + j] = v;
        }
    }
}

// ---------------- fused node_w/node_h contraction + token_fused MLP -----------
// block = (pg, b): handles points p = 2*pg, 2*pg+1; 256 threads = d.
// adj col p = padj_part0 + padj_part1 + nr_b2[p]  (fc2 split-K combine)
// single pass over the 12x12 compact grid feeds both node_w and node_h rows,
// then the folded 24->48->1 MLP produces token_fused[b,p,d].
__global__ __launch_bounds__(256)
void node_tf_fused(const float* __restrict__ t,        // token_init [4,144,256]
                   const float* __restrict__ nr_b2,
                   const float* __restrict__ w1, const float* __restrict__ b1,
                   const float* __restrict__ w2, const float* __restrict__ b2,
                   float rs2)
{
    __shared__ __align__(16) float2 adjc[M144];        // combined adj cols (p0,p1)
    __shared__ __align__(16) float  w1t[48][24];       // folded+transposed w1
    __shared__ float b1s[48];
    __shared__ float w2s[48];

    const int pg  = blockIdx.x;        // 0..63
    const int b   = blockIdx.y;        // 0..3
    const int tid = threadIdx.x;
    const int p0  = pg * 2;

    if (tid < M144) {
        long i0 = (long)(b * M144 + tid) * NP + p0;
        float a0 = g_padj[i0]     + g_padj[(long)MT * NP + i0]     + nr_b2[p0];
        float a1 = g_padj[i0 + 1] + g_padj[(long)MT * NP + i0 + 1] + nr_b2[p0 + 1];
        adjc[tid] = make_float2(a0, a1);
    }
    for (int idx = tid; idx < 48 * 24; idx += 256) {
        int j = idx / 24, i = idx % 24;
        w1t[j][i] = w1[(2 * i) * 48 + j] + w1[(2 * i + 1) * 48 + j];
    }
    if (tid < 48) { b1s[tid] = b1[tid]; w2s[tid] = w2[tid]; }
    __syncthreads();

    const int d = tid;
    const float* tb = t + ((long)b * M144) * DIM + d;

    float x0[24], x1[24];
#pragma unroll
    for (int i = 0; i < 24; i++) { x0[i] = 0.f; x1[i] = 0.f; }

#pragma unroll
    for (int h = 0; h < S0; h++) {
#pragma unroll
        for (int w = 0; w < S0; w++) {
            const int r = h * S0 + w;
            float tv = tb[(long)r * DIM];
            float2 a = adjc[r];
            float v0 = a.x * tv;
            float v1 = a.y * tv;
            x0[h]      += v0;  x1[h]      += v1;
            x0[12 + w] += v0;  x1[12 + w] += v1;
        }
    }
#pragma unroll
    for (int i = 0; i < 24; i++) { x0[i] *= rs2; x1[i] *= rs2; }

    const float bias2 = b2[0];
    float out0 = bias2, out1 = bias2;
    for (int j = 0; j < 48; j++) {
        float a0 = b1s[j], a1 = b1s[j];
        const float4* wr = (const float4*)&w1t[j][0];
#pragma unroll
        for (int i4 = 0; i4 < 6; i4++) {
            float4 wv = wr[i4];
            a0 += x0[i4 * 4 + 0] * wv.x + x0[i4 * 4 + 1] * wv.y
                + x0[i4 * 4 + 2] * wv.z + x0[i4 * 4 + 3] * wv.w;
            a1 += x1[i4 * 4 + 0] * wv.x + x1[i4 * 4 + 1] * wv.y
                + x1[i4 * 4 + 2] * wv.z + x1[i4 * 4 + 3] * wv.w;
        }
        float w2v = w2s[j];
        out0 += gelu_exact(a0) * w2v;
        out1 += gelu_exact(a1) * w2v;
    }
    g_fus[((long)(b * NP) + p0)     * DIM + d] = out0;
    g_fus[((long)(b * NP) + p0 + 1) * DIM + d] = out1;
}

// ---------------- softmax over 128 points, fused fc2 split-K combine ----------
__global__ __launch_bounds__(128)
void softmax_combine_kernel(const float* __restrict__ na_b2) {
    const int row = blockIdx.x;
    const int t = threadIdx.x;
    const long idx = (long)row * NP + t;
    float v = g_pattn[idx] + g_pattn[(long)MT * NP + idx] + na_b2[t];
    __shared__ float red[4];
    float m = v;
#pragma unroll
    for (int o = 16; o; o >>= 1) m = fmaxf(m, __shfl_xor_sync(0xffffffffu, m, o));
    if ((t & 31) == 0) red[t >> 5] = m;
    __syncthreads();
    m = fmaxf(fmaxf(red[0], red[1]), fmaxf(red[2], red[3]));
    float e = expf(v - m);
    __syncthreads();
    float s = e;
#pragma unroll
    for (int o = 16; o; o >>= 1) s += __shfl_xor_sync(0xffffffffu, s, o);
    if ((t & 31) == 0) red[t >> 5] = s;
    __syncthreads();
    s = red[0] + red[1] + red[2] + red[3];
    g_attn[idx] = e / s;
}

// ---------------- final scatter-broadcast of the 144 unique rows --------------
__global__ __launch_bounds__(256)
void scatter_kernel(float4* __restrict__ out) {
    const int wq = threadIdx.x >> 6;          // 0..3
    const int dq = threadIdx.x & 63;          // 0..63
    const int w  = blockIdx.x * 4 + wq;
    const int h  = blockIdx.y;
    const int b  = blockIdx.z;
    const int r  = (h / 10) * S0 + (3 * w) / 40;
    const float4* src = reinterpret_cast<const float4*>(g_U)
                        + (long)(b * M144 + r) * (DIM / 4);
    float4* dst = out + (long)(((b * H_) + h) * W_ + w) * (DIM / 4);
    dst[dq] = src[dq];
}

// ==============================================================================
extern "C" void kernel_launch(void* const* d_in, const int* in_sizes, int n_in,
                              void* d_out, int out_size) {
    const float* token_init  = (const float*)d_in[0];   // [4,12,12,256] == compact t
    const float* point_token = (const float*)d_in[1];
    const float* nr_w1 = (const float*)d_in[2];
    const float* nr_b1 = (const float*)d_in[3];
    const float* nr_w2 = (const float*)d_in[4];
    const float* nr_b2 = (const float*)d_in[5];
    const float* na_w1 = (const float*)d_in[6];
    const float* na_b1 = (const float*)d_in[7];
    const float* na_w2 = (const float*)d_in[8];
    const float* na_b2 = (const float*)d_in[9];
    const float* tf_w1 = (const float*)d_in[10];
    const float* tf_b1 = (const float*)d_in[11];
    const float* tf_w2 = (const float*)d_in[12];
    const float* tf_b2 = (const float*)d_in[13];
    float* out = (float*)d_out;

    float *A0_p, *H_p, *padj_p, *pattn_p, *attn_p, *fus_p, *U_p;
    cudaGetSymbolAddress((void**)&A0_p,   g_A0);
    cudaGetSymbolAddress((void**)&H_p,    g_H);
    cudaGetSymbolAddress((void**)&padj_p, g_padj);
    cudaGetSymbolAddress((void**)&pattn_p,g_pattn);
    cudaGetSymbolAddress((void**)&attn_p, g_attn);
    cudaGetSymbolAddress((void**)&fus_p,  g_fus);
    cudaGetSymbolAddress((void**)&U_p,    g_U);

    const float scale = 0.0625f;                    // dim^-0.5
    const float rs2   = 2.f * 0.20412414523193154f; // 2 * 24^-0.5

    // 1. A0 = t144 @ P^T * scale   [4*144,128]  (t144 == token_init)
    gemm_f32<16, 32, 16, 2, 4, true, false, false, false, false, 1>
        <<<dim3(NP / 32, M144 / 16, B_), 64>>>(
        token_init, point_token, nullptr, nullptr, nullptr, nullptr, A0_p, nullptr,
        DIM, scale,
        (long)M144 * DIM, DIM, 0,
        (long)NP * DIM, DIM,
        (long)M144 * NP, NP, 0,
        0, 0, 0);

    // 2. fc1 (nr & na): H = gelu(A0 @ w1 + b1)   [576,1024]
    gemm_f32<32, 64, 16, 4, 4, false, true, true, false, true, 1>
        <<<dim3(HID / 64, MT / 32, 2), 128>>>(
        A0_p, nr_w1, na_w1, nr_b1, na_b1, nullptr, H_p, H_p,
        NP, 1.f,
        0, NP, 0,
        0, HID,
        0, 2 * HID, HID,
        0, 0, 0);

    // 3. fc2 split-K2 (nr & na): raw partials (bias added by consumers)
    gemm_f32<32, 32, 16, 4, 2, false, false, false, false, true, 2>
        <<<dim3(NP / 32, MT / 32, 4), 128>>>(
        H_p, nr_w2, na_w2, nullptr, nullptr, nullptr, padj_p, pattn_p,
        HID, 1.f,
        0, 2 * HID, HID,
        0, NP,
        0, NP, 0,
        0, 0, (long)MT * NP);

    // 4. softmax (combines na partials + bias)   [576,128]
    softmax_combine_kernel<<<dim3(MT), 128>>>(na_b2);

    // 5. fused node contraction + token_fused MLP (combines nr partials + bias)
    node_tf_fused<<<dim3(NP / 2, B_), 256>>>(
        token_init, nr_b2, tf_w1, tf_b1, tf_w2, tf_b2, rs2);

    // 6. U = attn @ token_fused + t144   [4*144,256]
    gemm_f32<16, 64, 16, 2, 4, false, false, false, true, false, 1>
        <<<dim3(DIM / 64, M144 / 16, B_), 128>>>(
        attn_p, fus_p, nullptr, nullptr, nullptr, token_init, U_p, nullptr,
        NP, 1.f,
        (long)M144 * NP, NP, 0,
        (long)NP * DIM, DIM,
        (long)M144 * DIM, DIM, 0,
        (long)M144 * DIM, DIM, 0);

    // 7. broadcast unique rows to the full [4,19200,256] output
    scatter_kernel<<<dim3(W_ / 4, H_, B_), 256>>>((float4*)out);
}

// round 8
// speedup vs baseline: 1.4633x; 1.0816x over previous
#include <cuda_runtime.h>
#include <math.h>
#include <stdint.h>

// Problem constants (shapes fixed by the dataset)
#define B_    4
#define S0    12          // token_init side; compact row count per batch = 144
#define M144  144         // unique rows per batch
#define MT    576         // B_*M144
#define DIM   256
#define NP    128         // nPnt
#define HID   512         // 4*nPnt
#define H_    120
#define W_    160

typedef unsigned long long ull;

// ---------------- scratch (device globals) ------------------------------------
__device__ float g_A0   [MT * NP];             // compact t @ P^T / 16   [576,128]
__device__ float g_H    [MT * 2 * HID];        // hidden, nr [0,512) na [512,1024)
__device__ float g_padj [2 * MT * NP];         // fc2 nr partials (split-K halves)
__device__ float g_pattn[2 * MT * NP];         // fc2 na partials
__device__ float g_fus  [B_ * NP * DIM];       // token_fused [4,128,256]
__device__ float g_U    [MT * DIM];            // unique output rows [576,256]

__device__ __forceinline__ float gelu_exact(float x) {
    return 0.5f * x * (1.0f + erff(x * 0.70710678118654752440f));
}

// ===================== templated fp32 GEMM (R4-proven + split-K) ==============
// C = act( alpha * A @ B(^T) + bias ) + R
// DUAL: z-branch selects B0/B1, bias0/bias1, C0/C1, ofsA/ofsC.
// SPLITK: z also carries k-chunk; partial written at C + kc*sPart (no bias).
template<int BM, int BN, int BK, int TM, int TN,
         bool TRANSB, bool ACT, bool BIAS, bool RESID, bool DUAL, int SPLITK>
__global__ __launch_bounds__((BM / TM) * (BN / TN))
void gemm_f32(const float* __restrict__ A,
              const float* __restrict__ B0, const float* __restrict__ B1,
              const float* __restrict__ bias0, const float* __restrict__ bias1,
              const float* __restrict__ R,
              float* __restrict__ C0, float* __restrict__ C1,
              int K, float alpha,
              long sA, int lda, int ofsA,
              long sB, int ldb,
              long sC, int ldc, int ofsC,
              long sR, int ldr, long sPart)
{
    constexpr int THREADS = (BM / TM) * (BN / TN);
    constexpr int NA = (BM * BK) / THREADS;     // A elems per thread per tile
    constexpr int NB = (BN * BK) / THREADS;     // B elems per thread per tile
    static_assert(NA * THREADS == BM * BK, "A load divisibility");
    static_assert(NB * THREADS == BN * BK, "B load divisibility");

#if __CUDA_ARCH__ >= 900
    cudaGridDependencySynchronize();
#endif

    const int z  = blockIdx.z;
    const int kc = (SPLITK > 1) ? (z % SPLITK) : 0;
    const int r2 = (SPLITK > 1) ? (z / SPLITK) : z;
    const int br = DUAL ? (r2 & 1) : 0;
    const int bz = DUAL ? (r2 >> 1) : r2;

    const int Kc = K / SPLITK;

    const float* Bw  = (DUAL && br) ? B1 : B0;
    const float* bia = (DUAL && br) ? bias1 : bias0;
    float*       C   = (DUAL && br) ? C1 : C0;

    A  += (long)bz * sA + (long)br * ofsA + (long)kc * Kc;
    Bw += (long)bz * sB + (TRANSB ? (long)kc * Kc : (long)kc * Kc * ldb);
    C  += (long)bz * sC + (long)br * ofsC + (long)kc * sPart;
    const float* Rp = R + (long)bz * sR;

    __shared__ float As[BK][BM + 1];
    __shared__ float Bs[BK][BN + 1];

    const int tid  = threadIdx.x;
    const int row0 = blockIdx.y * BM;
    const int col0 = blockIdx.x * BN;
    const int tn   = tid % (BN / TN);
    const int tm   = tid / (BN / TN);
    const int m0   = tm * TM;
    const int n0   = tn * TN;

    float acc[TM][TN];
#pragma unroll
    for (int i = 0; i < TM; i++)
#pragma unroll
        for (int j = 0; j < TN; j++) acc[i][j] = 0.f;

    float regA[NA], regB[NB];
    const int nT = Kc / BK;

    // prologue: load tile 0 into regs
#pragma unroll
    for (int j = 0; j < NA; j++) {
        int idx = tid + j * THREADS;
        int r = idx / BK, k = idx % BK;
        regA[j] = A[(long)(row0 + r) * lda + k];
    }
#pragma unroll
    for (int j = 0; j < NB; j++) {
        int idx = tid + j * THREADS;
        if (TRANSB) { int n = idx / BK, k = idx % BK; regB[j] = Bw[(long)(col0 + n) * ldb + k]; }
        else        { int k = idx / BN, n = idx % BN; regB[j] = Bw[(long)k * ldb + col0 + n]; }
    }

    for (int t = 0; t < nT; t++) {
        // regs -> smem
#pragma unroll
        for (int j = 0; j < NA; j++) {
            int idx = tid + j * THREADS;
            int r = idx / BK, k = idx % BK;
            As[k][r] = regA[j];
        }
#pragma unroll
        for (int j = 0; j < NB; j++) {
            int idx = tid + j * THREADS;
            if (TRANSB) { int n = idx / BK, k = idx % BK; Bs[k][n] = regB[j]; }
            else        { int k = idx / BN, n = idx % BN; Bs[k][n] = regB[j]; }
        }
        __syncthreads();

        // prefetch next tile
        if (t + 1 < nT) {
            const int k0 = (t + 1) * BK;
#pragma unroll
            for (int j = 0; j < NA; j++) {
                int idx = tid + j * THREADS;
                int r = idx / BK, k = idx % BK;
                regA[j] = A[(long)(row0 + r) * lda + k0 + k];
            }
#pragma unroll
            for (int j = 0; j < NB; j++) {
                int idx = tid + j * THREADS;
                if (TRANSB) { int n = idx / BK, k = idx % BK; regB[j] = Bw[(long)(col0 + n) * ldb + k0 + k]; }
                else        { int k = idx / BN, n = idx % BN; regB[j] = Bw[(long)(k0 + k) * ldb + col0 + n]; }
            }
        }

        // compute
#pragma unroll
        for (int kk = 0; kk < BK; kk++) {
            float av[TM], bv[TN];
#pragma unroll
            for (int i = 0; i < TM; i++) av[i] = As[kk][m0 + i];
#pragma unroll
            for (int j = 0; j < TN; j++) bv[j] = Bs[kk][n0 + j];
#pragma unroll
            for (int i = 0; i < TM; i++)
#pragma unroll
                for (int j = 0; j < TN; j++)
                    acc[i][j] += av[i] * bv[j];
        }
        __syncthreads();
    }

    // epilogue
    float bf[TN];
#pragma unroll
    for (int j = 0; j < TN; j++) bf[j] = BIAS ? bia[col0 + n0 + j] : 0.f;
#pragma unroll
    for (int i = 0; i < TM; i++) {
        const int row = row0 + m0 + i;
#pragma unroll
        for (int j = 0; j < TN; j++) {
            float v = acc[i][j] * alpha + bf[j];
            if (ACT)   v = gelu_exact(v);
            if (RESID) v += Rp[(long)row * ldr + col0 + n0 + j];
            C[(long)row * ldc + col0 + n0 + j] = v;
        }
    }
}

// ---------------- fused node_w/node_h contraction + token_fused MLP -----------
// block = (pg, b): handles points p = 2*pg, 2*pg+1; 256 threads = d.
// adj col p = padj_part0 + padj_part1 + nr_b2[p]  (fc2 split-K combine)
__global__ __launch_bounds__(256)
void node_tf_fused(const float* __restrict__ t,        // token_init [4,144,256]
                   const float* __restrict__ nr_b2,
                   const float* __restrict__ w1, const float* __restrict__ b1,
                   const float* __restrict__ w2, const float* __restrict__ b2,
                   float rs2)
{
#if __CUDA_ARCH__ >= 900
    cudaGridDependencySynchronize();
#endif
    __shared__ __align__(16) float2 adjc[M144];        // combined adj cols (p0,p1)
    __shared__ __align__(16) float  w1t[48][24];       // folded+transposed w1
    __shared__ float b1s[48];
    __shared__ float w2s[48];

    const int pg  = blockIdx.x;        // 0..63
    const int b   = blockIdx.y;        // 0..3
    const int tid = threadIdx.x;
    const int p0  = pg * 2;

    if (tid < M144) {
        long i0 = (long)(b * M144 + tid) * NP + p0;
        float a0 = g_padj[i0]     + g_padj[(long)MT * NP + i0]     + nr_b2[p0];
        float a1 = g_padj[i0 + 1] + g_padj[(long)MT * NP + i0 + 1] + nr_b2[p0 + 1];
        adjc[tid] = make_float2(a0, a1);
    }
    for (int idx = tid; idx < 48 * 24; idx += 256) {
        int j = idx / 24, i = idx % 24;
        w1t[j][i] = w1[(2 * i) * 48 + j] + w1[(2 * i + 1) * 48 + j];
    }
    if (tid < 48) { b1s[tid] = b1[tid]; w2s[tid] = w2[tid]; }
    __syncthreads();

    const int d = tid;
    const float* tb = t + ((long)b * M144) * DIM + d;

    float x0[24], x1[24];
#pragma unroll
    for (int i = 0; i < 24; i++) { x0[i] = 0.f; x1[i] = 0.f; }

#pragma unroll
    for (int h = 0; h < S0; h++) {
#pragma unroll
        for (int w = 0; w < S0; w++) {
            const int r = h * S0 + w;
            float tv = tb[(long)r * DIM];
            float2 a = adjc[r];
            float v0 = a.x * tv;
            float v1 = a.y * tv;
            x0[h]      += v0;  x1[h]      += v1;
            x0[12 + w] += v0;  x1[12 + w] += v1;
        }
    }
#pragma unroll
    for (int i = 0; i < 24; i++) { x0[i] *= rs2; x1[i] *= rs2; }

    const float bias2 = b2[0];
    float out0 = bias2, out1 = bias2;
    for (int j = 0; j < 48; j++) {
        float a0 = b1s[j], a1 = b1s[j];
        const float4* wr = (const float4*)&w1t[j][0];
#pragma unroll
        for (int i4 = 0; i4 < 6; i4++) {
            float4 wv = wr[i4];
            a0 += x0[i4 * 4 + 0] * wv.x + x0[i4 * 4 + 1] * wv.y
                + x0[i4 * 4 + 2] * wv.z + x0[i4 * 4 + 3] * wv.w;
            a1 += x1[i4 * 4 + 0] * wv.x + x1[i4 * 4 + 1] * wv.y
                + x1[i4 * 4 + 2] * wv.z + x1[i4 * 4 + 3] * wv.w;
        }
        float w2v = w2s[j];
        out0 += gelu_exact(a0) * w2v;
        out1 += gelu_exact(a1) * w2v;
    }
    g_fus[((long)(b * NP) + p0)     * DIM + d] = out0;
    g_fus[((long)(b * NP) + p0 + 1) * DIM + d] = out1;
}

// ---------------- U = softmax(fc2_na) @ fus + t, softmax fused ----------------
// grid (DIM/64, M144/16, B_), 128 threads. Combines fc2 na split-K partials,
// softmaxes each of its 16 rows (8-lane groups), stages the 128x64 fus panel
// in smem, then does the K=128 GEMM with residual epilogue.
__global__ __launch_bounds__(128)
void u_softmax_gemm(const float* __restrict__ na_b2,
                    const float* __restrict__ t)
{
#if __CUDA_ARCH__ >= 900
    cudaGridDependencySynchronize();
#endif
    __shared__ float As[NP][17];        // softmaxed attn, [k][row]  (8.7 KB)
    __shared__ __align__(16) float Bs[NP][68];   // fus panel [k][col] (34.8 KB)

    const int cb  = blockIdx.x;
    const int rb  = blockIdx.y;
    const int b   = blockIdx.z;
    const int tid = threadIdx.x;
    const int row0 = rb * 16;
    const int col0 = cb * 64;

    // stage B panel: fus[b, k, col0..col0+63]
    {
        const float* fb = g_fus + ((long)b * NP) * DIM + col0;
        for (int idx = tid; idx < NP * 16; idx += 128) {
            int k = idx >> 4, c4 = (idx & 15) * 4;
            float4 v = *(const float4*)&fb[(long)k * DIM + c4];
            *(float4*)&Bs[k][c4] = v;
        }
    }

    // combine split-K + bias, softmax rows (8 threads per row)
    {
        const int lr  = tid >> 3;          // 0..15 local row
        const int sub = tid & 7;           // 8 lanes per row
        const long rbase = ((long)(b * M144) + row0 + lr) * NP;
        float v[16];
        float mx = -1e30f;
#pragma unroll
        for (int i = 0; i < 16; i++) {
            int k = sub * 16 + i;
            v[i] = g_pattn[rbase + k] + g_pattn[(long)MT * NP + rbase + k] + na_b2[k];
            mx = fmaxf(mx, v[i]);
        }
#pragma unroll
        for (int o = 1; o < 8; o <<= 1) mx = fmaxf(mx, __shfl_xor_sync(0xffffffffu, mx, o));
        float sum = 0.f;
#pragma unroll
        for (int i = 0; i < 16; i++) { v[i] = expf(v[i] - mx); sum += v[i]; }
#pragma unroll
        for (int o = 1; o < 8; o <<= 1) sum += __shfl_xor_sync(0xffffffffu, sum, o);
        float inv = 1.f / sum;
#pragma unroll
        for (int i = 0; i < 16; i++) As[sub * 16 + i][lr] = v[i] * inv;
    }
    __syncthreads();

    // GEMM: 16x64 output, TM=2 TN=4
    const int tm = tid >> 4;           // 0..7
    const int tn = tid & 15;           // 0..15
    const int m0 = tm * 2;
    const int n0 = tn * 4;

    float acc[2][4];
#pragma unroll
    for (int i = 0; i < 2; i++)
#pragma unroll
        for (int j = 0; j < 4; j++) acc[i][j] = 0.f;

#pragma unroll 8
    for (int k = 0; k < NP; k++) {
        float a0 = As[k][m0], a1 = As[k][m0 + 1];
        float4 bb = *(const float4*)&Bs[k][n0];
        acc[0][0] += a0 * bb.x; acc[0][1] += a0 * bb.y;
        acc[0][2] += a0 * bb.z; acc[0][3] += a0 * bb.w;
        acc[1][0] += a1 * bb.x; acc[1][1] += a1 * bb.y;
        acc[1][2] += a1 * bb.z; acc[1][3] += a1 * bb.w;
    }

#pragma unroll
    for (int i = 0; i < 2; i++) {
        const int row = row0 + m0 + i;
        const float4 r = *(const float4*)&t[((long)(b * M144) + row) * DIM + col0 + n0];
        float4 v;
        v.x = acc[i][0] + r.x; v.y = acc[i][1] + r.y;
        v.z = acc[i][2] + r.z; v.w = acc[i][3] + r.w;
        *(float4*)&g_U[((long)(b * M144) + row) * DIM + col0 + n0] = v;
    }
}

// ---------------- final scatter-broadcast of the 144 unique rows --------------
__global__ __launch_bounds__(256)
void scatter_kernel(float4* __restrict__ out) {
#if __CUDA_ARCH__ >= 900
    cudaGridDependencySynchronize();
#endif
    const int wq = threadIdx.x >> 6;          // 0..3
    const int dq = threadIdx.x & 63;          // 0..63
    const int w  = blockIdx.x * 4 + wq;
    const int h  = blockIdx.y;
    const int b  = blockIdx.z;
    const int r  = (h / 10) * S0 + (3 * w) / 40;
    const float4* src = reinterpret_cast<const float4*>(g_U)
                        + (long)(b * M144 + r) * (DIM / 4);
    float4* dst = out + (long)(((b * H_) + h) * W_ + w) * (DIM / 4);
    dst[dq] = src[dq];
}

// ---------------- PDL launch helper -------------------------------------------
template<typename K, typename... A>
static void launch_pdl(dim3 g, dim3 blk, K kern, A... args) {
    cudaLaunchConfig_t cfg = {};
    cfg.gridDim = g;
    cfg.blockDim = blk;
    cfg.dynamicSmemBytes = 0;
    cfg.stream = 0;
    cudaLaunchAttribute at;
    at.id = cudaLaunchAttributeProgrammaticStreamSerialization;
    at.val.programmaticStreamSerializationAllowed = 1;
    cfg.attrs = &at;
    cfg.numAttrs = 1;
    cudaLaunchKernelEx(&cfg, kern, args...);
}

// ==============================================================================
extern "C" void kernel_launch(void* const* d_in, const int* in_sizes, int n_in,
                              void* d_out, int out_size) {
    const float* token_init  = (const float*)d_in[0];   // [4,12,12,256] == compact t
    const float* point_token = (const float*)d_in[1];
    const float* nr_w1 = (const float*)d_in[2];
    const float* nr_b1 = (const float*)d_in[3];
    const float* nr_w2 = (const float*)d_in[4];
    const float* nr_b2 = (const float*)d_in[5];
    const float* na_w1 = (const float*)d_in[6];
    const float* na_b1 = (const float*)d_in[7];
    const float* na_w2 = (const float*)d_in[8];
    const float* na_b2 = (const float*)d_in[9];
    const float* tf_w1 = (const float*)d_in[10];
    const float* tf_b1 = (const float*)d_in[11];
    const float* tf_w2 = (const float*)d_in[12];
    const float* tf_b2 = (const float*)d_in[13];
    float* out = (float*)d_out;

    float *A0_p, *H_p, *padj_p, *pattn_p;
    cudaGetSymbolAddress((void**)&A0_p,   g_A0);
    cudaGetSymbolAddress((void**)&H_p,    g_H);
    cudaGetSymbolAddress((void**)&padj_p, g_padj);
    cudaGetSymbolAddress((void**)&pattn_p,g_pattn);

    const float scale = 0.0625f;                    // dim^-0.5
    const float rs2   = 2.f * 0.20412414523193154f; // 2 * 24^-0.5

    // 1. A0 = t144 @ P^T * scale   [4*144,128]
    launch_pdl(dim3(NP / 32, M144 / 16, B_), dim3(64),
        gemm_f32<16, 32, 16, 2, 4, true, false, false, false, false, 1>,
        token_init, point_token, (const float*)nullptr,
        (const float*)nullptr, (const float*)nullptr, (const float*)nullptr,
        A0_p, (float*)nullptr,
        (int)DIM, scale,
        (long)M144 * DIM, (int)DIM, 0,
        (long)NP * DIM, (int)DIM,
        (long)M144 * NP, (int)NP, 0,
        (long)0, 0, (long)0);

    // 2. fc1 (nr & na): H = gelu(A0 @ w1 + b1)   [576,1024]
    launch_pdl(dim3(HID / 64, MT / 32, 2), dim3(128),
        gemm_f32<32, 64, 16, 4, 4, false, true, true, false, true, 1>,
        (const float*)A0_p, nr_w1, na_w1, nr_b1, na_b1, (const float*)nullptr,
        H_p, H_p,
        (int)NP, 1.f,
        (long)0, (int)NP, 0,
        (long)0, (int)HID,
        (long)0, (int)(2 * HID), (int)HID,
        (long)0, 0, (long)0);

    // 3. fc2 split-K2 (nr & na): raw partials (bias added by consumers)
    launch_pdl(dim3(NP / 32, MT / 32, 4), dim3(128),
        gemm_f32<32, 32, 16, 4, 2, false, false, false, false, true, 2>,
        (const float*)H_p, nr_w2, na_w2,
        (const float*)nullptr, (const float*)nullptr, (const float*)nullptr,
        padj_p, pattn_p,
        (int)HID, 1.f,
        (long)0, (int)(2 * HID), (int)HID,
        (long)0, (int)NP,
        (long)0, (int)NP, 0,
        (long)0, 0, (long)MT * NP);

    // 4. fused node contraction + token_fused MLP (combines nr partials + bias)
    launch_pdl(dim3(NP / 2, B_), dim3(256),
        node_tf_fused,
        token_init, nr_b2, tf_w1, tf_b1, tf_w2, tf_b2, rs2);

    // 5. U = softmax(na partials + bias) @ fus + t144   [4*144,256]
    launch_pdl(dim3(DIM / 64, M144 / 16, B_), dim3(128),
        u_softmax_gemm, na_b2, token_init);

    // 6. broadcast unique rows to the full [4,19200,256] output
    launch_pdl(dim3(W_ / 4, H_, B_), dim3(256),
        scatter_kernel, (float4*)out);
}

// round 9
// speedup vs baseline: 1.4696x; 1.0043x over previous
#include <cuda_runtime.h>
#include <math.h>
#include <stdint.h>

// Problem constants (shapes fixed by the dataset)
#define B_    4
#define S0    12          // token_init side; compact row count per batch = 144
#define M144  144         // unique rows per batch
#define MT    576         // B_*M144
#define DIM   256
#define NP    128         // nPnt
#define HID   512         // 4*nPnt
#define H_    120
#define W_    160

typedef unsigned long long ull;

// ---------------- scratch (device globals) ------------------------------------
__device__ float g_A0   [MT * NP];             // compact t @ P^T / 16   [576,128]
__device__ float g_H    [MT * 2 * HID];        // hidden, nr [0,512) na [512,1024)
__device__ float g_padj [2 * MT * NP];         // fc2 nr partials (split-K halves)
__device__ float g_pattn[2 * MT * NP];         // fc2 na partials
__device__ float g_fus  [B_ * NP * DIM];       // token_fused [4,128,256]
__device__ float g_U    [MT * DIM];            // unique output rows [576,256]

__device__ __forceinline__ float gelu_exact(float x) {
    return 0.5f * x * (1.0f + erff(x * 0.70710678118654752440f));
}
__device__ __forceinline__ ull pack2(float x, float y) {
    ull r; asm("mov.b64 %0, {%1, %2};" : "=l"(r) : "f"(x), "f"(y)); return r;
}
__device__ __forceinline__ void unpack2(ull v, float& x, float& y) {
    asm("mov.b64 {%0, %1}, %2;" : "=f"(x), "=f"(y) : "l"(v));
}
__device__ __forceinline__ ull fma2(ull a, ull b, ull c) {
    ull d; asm("fma.rn.f32x2 %0, %1, %2, %3;" : "=l"(d) : "l"(a), "l"(b), "l"(c));
    return d;
}

// ===================== templated fp32 GEMM (R4-proven + split-K) ==============
template<int BM, int BN, int BK, int TM, int TN,
         bool TRANSB, bool ACT, bool BIAS, bool RESID, bool DUAL, int SPLITK>
__global__ __launch_bounds__((BM / TM) * (BN / TN))
void gemm_f32(const float* __restrict__ A,
              const float* __restrict__ B0, const float* __restrict__ B1,
              const float* __restrict__ bias0, const float* __restrict__ bias1,
              const float* __restrict__ R,
              float* __restrict__ C0, float* __restrict__ C1,
              int K, float alpha,
              long sA, int lda, int ofsA,
              long sB, int ldb,
              long sC, int ldc, int ofsC,
              long sR, int ldr, long sPart)
{
    constexpr int THREADS = (BM / TM) * (BN / TN);
    constexpr int NA = (BM * BK) / THREADS;
    constexpr int NB = (BN * BK) / THREADS;
    static_assert(NA * THREADS == BM * BK, "A load divisibility");
    static_assert(NB * THREADS == BN * BK, "B load divisibility");

#if __CUDA_ARCH__ >= 900
    cudaGridDependencySynchronize();
#endif

    const int z  = blockIdx.z;
    const int kc = (SPLITK > 1) ? (z % SPLITK) : 0;
    const int r2 = (SPLITK > 1) ? (z / SPLITK) : z;
    const int br = DUAL ? (r2 & 1) : 0;
    const int bz = DUAL ? (r2 >> 1) : r2;

    const int Kc = K / SPLITK;

    const float* Bw  = (DUAL && br) ? B1 : B0;
    const float* bia = (DUAL && br) ? bias1 : bias0;
    float*       C   = (DUAL && br) ? C1 : C0;

    A  += (long)bz * sA + (long)br * ofsA + (long)kc * Kc;
    Bw += (long)bz * sB + (TRANSB ? (long)kc * Kc : (long)kc * Kc * ldb);
    C  += (long)bz * sC + (long)br * ofsC + (long)kc * sPart;
    const float* Rp = R + (long)bz * sR;

    __shared__ float As[BK][BM + 1];
    __shared__ float Bs[BK][BN + 1];

    const int tid  = threadIdx.x;
    const int row0 = blockIdx.y * BM;
    const int col0 = blockIdx.x * BN;
    const int tn   = tid % (BN / TN);
    const int tm   = tid / (BN / TN);
    const int m0   = tm * TM;
    const int n0   = tn * TN;

    float acc[TM][TN];
#pragma unroll
    for (int i = 0; i < TM; i++)
#pragma unroll
        for (int j = 0; j < TN; j++) acc[i][j] = 0.f;

    float regA[NA], regB[NB];
    const int nT = Kc / BK;

#pragma unroll
    for (int j = 0; j < NA; j++) {
        int idx = tid + j * THREADS;
        int r = idx / BK, k = idx % BK;
        regA[j] = A[(long)(row0 + r) * lda + k];
    }
#pragma unroll
    for (int j = 0; j < NB; j++) {
        int idx = tid + j * THREADS;
        if (TRANSB) { int n = idx / BK, k = idx % BK; regB[j] = Bw[(long)(col0 + n) * ldb + k]; }
        else        { int k = idx / BN, n = idx % BN; regB[j] = Bw[(long)k * ldb + col0 + n]; }
    }

    for (int t = 0; t < nT; t++) {
#pragma unroll
        for (int j = 0; j < NA; j++) {
            int idx = tid + j * THREADS;
            int r = idx / BK, k = idx % BK;
            As[k][r] = regA[j];
        }
#pragma unroll
        for (int j = 0; j < NB; j++) {
            int idx = tid + j * THREADS;
            if (TRANSB) { int n = idx / BK, k = idx % BK; Bs[k][n] = regB[j]; }
            else        { int k = idx / BN, n = idx % BN; Bs[k][n] = regB[j]; }
        }
        __syncthreads();

        if (t + 1 < nT) {
            const int k0 = (t + 1) * BK;
#pragma unroll
            for (int j = 0; j < NA; j++) {
                int idx = tid + j * THREADS;
                int r = idx / BK, k = idx % BK;
                regA[j] = A[(long)(row0 + r) * lda + k0 + k];
            }
#pragma unroll
            for (int j = 0; j < NB; j++) {
                int idx = tid + j * THREADS;
                if (TRANSB) { int n = idx / BK, k = idx % BK; regB[j] = Bw[(long)(col0 + n) * ldb + k0 + k]; }
                else        { int k = idx / BN, n = idx % BN; regB[j] = Bw[(long)(k0 + k) * ldb + col0 + n]; }
            }
        }

#pragma unroll
        for (int kk = 0; kk < BK; kk++) {
            float av[TM], bv[TN];
#pragma unroll
            for (int i = 0; i < TM; i++) av[i] = As[kk][m0 + i];
#pragma unroll
            for (int j = 0; j < TN; j++) bv[j] = Bs[kk][n0 + j];
#pragma unroll
            for (int i = 0; i < TM; i++)
#pragma unroll
                for (int j = 0; j < TN; j++)
                    acc[i][j] += av[i] * bv[j];
        }
        __syncthreads();
    }

    float bf[TN];
#pragma unroll
    for (int j = 0; j < TN; j++) bf[j] = BIAS ? bia[col0 + n0 + j] : 0.f;
#pragma unroll
    for (int i = 0; i < TM; i++) {
        const int row = row0 + m0 + i;
#pragma unroll
        for (int j = 0; j < TN; j++) {
            float v = acc[i][j] * alpha + bf[j];
            if (ACT)   v = gelu_exact(v);
            if (RESID) v += Rp[(long)row * ldr + col0 + n0 + j];
            C[(long)row * ldc + col0 + n0 + j] = v;
        }
    }
}

// ---------------- fused node contraction + token_fused MLP (packed f32x2) -----
// grid (NP, B_) = 512 blocks, 128 threads; block = one point p, thread = d-pair.
// adj col p = (padj_part0 + padj_part1 + nr_b2[p]) * rs2  (scale folded in)
__global__ __launch_bounds__(128)
void node_tf_fused(const float* __restrict__ t,        // token_init [4,144,256]
                   const float* __restrict__ nr_b2,
                   const float* __restrict__ w1, const float* __restrict__ b1,
                   const float* __restrict__ w2, const float* __restrict__ b2,
                   float rs2)
{
#if __CUDA_ARCH__ >= 900
    cudaGridDependencySynchronize();
#endif
    __shared__ __align__(16) ull adjc[M144];           // (a*rs2, a*rs2) packed
    __shared__ __align__(16) ull w1p[48][24];          // folded w1, (w,w) packed
    __shared__ ull  b1p[48];                           // (b1,b1) packed
    __shared__ float w2s[48];

    const int p   = blockIdx.x;        // 0..127
    const int b   = blockIdx.y;        // 0..3
    const int tid = threadIdx.x;       // 0..127

    // combined adj column (fc2 split-K + bias), rs2 folded in
    {
        const int m = tid;             // 0..127
        long i0 = (long)(b * M144 + m) * NP + p;
        float a = (g_padj[i0] + g_padj[(long)MT * NP + i0] + nr_b2[p]) * rs2;
        adjc[m] = pack2(a, a);
        if (tid < M144 - 128) {
            const int m2 = 128 + tid;
            long i1 = (long)(b * M144 + m2) * NP + p;
            float a2 = (g_padj[i1] + g_padj[(long)MT * NP + i1] + nr_b2[p]) * rs2;
            adjc[m2] = pack2(a2, a2);
        }
    }
    // folded + packed w1
    for (int idx = tid; idx < 48 * 24; idx += 128) {
        int j = idx / 24, i = idx % 24;
        float wv = w1[(2 * i) * 48 + j] + w1[(2 * i + 1) * 48 + j];
        w1p[j][i] = pack2(wv, wv);
    }
    if (tid < 48) {
        float bv = b1[tid];
        b1p[tid] = pack2(bv, bv);
        w2s[tid] = w2[tid];
    }
    __syncthreads();

    const int d0 = tid * 2;
    const ull* tb = (const ull*)(t + ((long)b * M144) * DIM + d0);

    // contraction: x[h] and x[12+w] accumulate a*t over the 12x12 grid
    ull x[24];
#pragma unroll
    for (int i = 0; i < 24; i++) x[i] = 0ull;

#pragma unroll
    for (int h = 0; h < S0; h++) {
#pragma unroll
        for (int w = 0; w < S0; w++) {
            const int r = h * S0 + w;
            ull tv2 = tb[(long)r * (DIM / 2)];
            ull a2  = adjc[r];
            x[h]      = fma2(a2, tv2, x[h]);
            x[12 + w] = fma2(a2, tv2, x[12 + w]);
        }
    }

    // MLP: 24 -> 48 (gelu) -> 1 ; two j-chains for ILP
    const float bias2 = b2[0];
    float out0 = bias2, out1 = bias2;
#pragma unroll 2
    for (int j = 0; j < 48; j += 2) {
        ull accA = b1p[j];
        ull accB = b1p[j + 1];
        const ulonglong2* wrA = (const ulonglong2*)&w1p[j][0];
        const ulonglong2* wrB = (const ulonglong2*)&w1p[j + 1][0];
#pragma unroll
        for (int i2 = 0; i2 < 12; i2++) {
            ulonglong2 wa = wrA[i2];
            ulonglong2 wb = wrB[i2];
            accA = fma2(x[2 * i2],     wa.x, accA);
            accB = fma2(x[2 * i2],     wb.x, accB);
            accA = fma2(x[2 * i2 + 1], wa.y, accA);
            accB = fma2(x[2 * i2 + 1], wb.y, accB);
        }
        float a0, a1, c0, c1;
        unpack2(accA, a0, a1);
        unpack2(accB, c0, c1);
        float wA = w2s[j], wB = w2s[j + 1];
        out0 += gelu_exact(a0) * wA;
        out1 += gelu_exact(a1) * wA;
        out0 += gelu_exact(c0) * wB;
        out1 += gelu_exact(c1) * wB;
    }
    *(float2*)&g_fus[((long)(b * NP) + p) * DIM + d0] = make_float2(out0, out1);
}

// ---------------- U = softmax(fc2_na) @ fus + t, softmax fused ----------------
__global__ __launch_bounds__(128)
void u_softmax_gemm(const float* __restrict__ na_b2,
                    const float* __restrict__ t)
{
#if __CUDA_ARCH__ >= 900
    cudaGridDependencySynchronize();
#endif
    __shared__ float As[NP][17];        // softmaxed attn, [k][row]
    __shared__ __align__(16) float Bs[NP][68];   // fus panel [k][col]

    const int cb  = blockIdx.x;
    const int rb  = blockIdx.y;
    const int b   = blockIdx.z;
    const int tid = threadIdx.x;
    const int row0 = rb * 16;
    const int col0 = cb * 64;

    {
        const float* fb = g_fus + ((long)b * NP) * DIM + col0;
        for (int idx = tid; idx < NP * 16; idx += 128) {
            int k = idx >> 4, c4 = (idx & 15) * 4;
            float4 v = *(const float4*)&fb[(long)k * DIM + c4];
            *(float4*)&Bs[k][c4] = v;
        }
    }

    {
        const int lr  = tid >> 3;
        const int sub = tid & 7;
        const long rbase = ((long)(b * M144) + row0 + lr) * NP;
        float v[16];
        float mx = -1e30f;
#pragma unroll
        for (int i = 0; i < 16; i++) {
            int k = sub * 16 + i;
            v[i] = g_pattn[rbase + k] + g_pattn[(long)MT * NP + rbase + k] + na_b2[k];
            mx = fmaxf(mx, v[i]);
        }
#pragma unroll
        for (int o = 1; o < 8; o <<= 1) mx = fmaxf(mx, __shfl_xor_sync(0xffffffffu, mx, o));
        float sum = 0.f;
#pragma unroll
        for (int i = 0; i < 16; i++) { v[i] = expf(v[i] - mx); sum += v[i]; }
#pragma unroll
        for (int o = 1; o < 8; o <<= 1) sum += __shfl_xor_sync(0xffffffffu, sum, o);
        float inv = 1.f / sum;
#pragma unroll
        for (int i = 0; i < 16; i++) As[sub * 16 + i][lr] = v[i] * inv;
    }
    __syncthreads();

    const int tm = tid >> 4;
    const int tn = tid & 15;
    const int m0 = tm * 2;
    const int n0 = tn * 4;

    float acc[2][4];
#pragma unroll
    for (int i = 0; i < 2; i++)
#pragma unroll
        for (int j = 0; j < 4; j++) acc[i][j] = 0.f;

#pragma unroll 8
    for (int k = 0; k < NP; k++) {
        float a0 = As[k][m0], a1 = As[k][m0 + 1];
        float4 bb = *(const float4*)&Bs[k][n0];
        acc[0][0] += a0 * bb.x; acc[0][1] += a0 * bb.y;
        acc[0][2] += a0 * bb.z; acc[0][3] += a0 * bb.w;
        acc[1][0] += a1 * bb.x; acc[1][1] += a1 * bb.y;
        acc[1][2] += a1 * bb.z; acc[1][3] += a1 * bb.w;
    }

#pragma unroll
    for (int i = 0; i < 2; i++) {
        const int row = row0 + m0 + i;
        const float4 r = *(const float4*)&t[((long)(b * M144) + row) * DIM + col0 + n0];
        float4 v;
        v.x = acc[i][0] + r.x; v.y = acc[i][1] + r.y;
        v.z = acc[i][2] + r.z; v.w = acc[i][3] + r.w;
        *(float4*)&g_U[((long)(b * M144) + row) * DIM + col0 + n0] = v;
    }
}

// ---------------- final scatter-broadcast of the 144 unique rows --------------
__global__ __launch_bounds__(256)
void scatter_kernel(float4* __restrict__ out) {
#if __CUDA_ARCH__ >= 900
    cudaGridDependencySynchronize();
#endif
    const int wq = threadIdx.x >> 6;
    const int dq = threadIdx.x & 63;
    const int w  = blockIdx.x * 4 + wq;
    const int h  = blockIdx.y;
    const int b  = blockIdx.z;
    const int r  = (h / 10) * S0 + (3 * w) / 40;
    const float4* src = reinterpret_cast<const float4*>(g_U)
                        + (long)(b * M144 + r) * (DIM / 4);
    float4* dst = out + (long)(((b * H_) + h) * W_ + w) * (DIM / 4);
    dst[dq] = src[dq];
}

// ---------------- PDL launch helper -------------------------------------------
template<typename K, typename... A>
static void launch_pdl(dim3 g, dim3 blk, K kern, A... args) {
    cudaLaunchConfig_t cfg = {};
    cfg.gridDim = g;
    cfg.blockDim = blk;
    cfg.dynamicSmemBytes = 0;
    cfg.stream = 0;
    cudaLaunchAttribute at;
    at.id = cudaLaunchAttributeProgrammaticStreamSerialization;
    at.val.programmaticStreamSerializationAllowed = 1;
    cfg.attrs = &at;
    cfg.numAttrs = 1;
    cudaLaunchKernelEx(&cfg, kern, args...);
}

// ==============================================================================
extern "C" void kernel_launch(void* const* d_in, const int* in_sizes, int n_in,
                              void* d_out, int out_size) {
    const float* token_init  = (const float*)d_in[0];   // [4,12,12,256] == compact t
    const float* point_token = (const float*)d_in[1];
    const float* nr_w1 = (const float*)d_in[2];
    const float* nr_b1 = (const float*)d_in[3];
    const float* nr_w2 = (const float*)d_in[4];
    const float* nr_b2 = (const float*)d_in[5];
    const float* na_w1 = (const float*)d_in[6];
    const float* na_b1 = (const float*)d_in[7];
    const float* na_w2 = (const float*)d_in[8];
    const float* na_b2 = (const float*)d_in[9];
    const float* tf_w1 = (const float*)d_in[10];
    const float* tf_b1 = (const float*)d_in[11];
    const float* tf_w2 = (const float*)d_in[12];
    const float* tf_b2 = (const float*)d_in[13];
    float* out = (float*)d_out;

    float *A0_p, *H_p, *padj_p, *pattn_p;
    cudaGetSymbolAddress((void**)&A0_p,   g_A0);
    cudaGetSymbolAddress((void**)&H_p,    g_H);
    cudaGetSymbolAddress((void**)&padj_p, g_padj);
    cudaGetSymbolAddress((void**)&pattn_p,g_pattn);

    const float scale = 0.0625f;                    // dim^-0.5
    const float rs2   = 2.f * 0.20412414523193154f; // 2 * 24^-0.5

    // 1. A0 = t144 @ P^T * scale   [4*144,128]
    launch_pdl(dim3(NP / 32, M144 / 16, B_), dim3(64),
        gemm_f32<16, 32, 16, 2, 4, true, false, false, false, false, 1>,
        token_init, point_token, (const float*)nullptr,
        (const float*)nullptr, (const float*)nullptr, (const float*)nullptr,
        A0_p, (float*)nullptr,
        (int)DIM, scale,
        (long)M144 * DIM, (int)DIM, 0,
        (long)NP * DIM, (int)DIM,
        (long)M144 * NP, (int)NP, 0,
        (long)0, 0, (long)0);

    // 2. fc1 (nr & na): H = gelu(A0 @ w1 + b1)   [576,1024]
    launch_pdl(dim3(HID / 64, MT / 32, 2), dim3(128),
        gemm_f32<32, 64, 16, 4, 4, false, true, true, false, true, 1>,
        (const float*)A0_p, nr_w1, na_w1, nr_b1, na_b1, (const float*)nullptr,
        H_p, H_p,
        (int)NP, 1.f,
        (long)0, (int)NP, 0,
        (long)0, (int)HID,
        (long)0, (int)(2 * HID), (int)HID,
        (long)0, 0, (long)0);

    // 3. fc2 split-K2 (nr & na): raw partials (bias added by consumers)
    launch_pdl(dim3(NP / 32, MT / 32, 4), dim3(128),
        gemm_f32<32, 32, 16, 4, 2, false, false, false, false, true, 2>,
        (const float*)H_p, nr_w2, na_w2,
        (const float*)nullptr, (const float*)nullptr, (const float*)nullptr,
        padj_p, pattn_p,
        (int)HID, 1.f,
        (long)0, (int)(2 * HID), (int)HID,
        (long)0, (int)NP,
        (long)0, (int)NP, 0,
        (long)0, 0, (long)MT * NP);

    // 4. fused node contraction + token_fused MLP (combines nr partials + bias)
    launch_pdl(dim3(NP, B_), dim3(128),
        node_tf_fused,
        token_init, nr_b2, tf_w1, tf_b1, tf_w2, tf_b2, rs2);

    // 5. U = softmax(na partials + bias) @ fus + t144   [4*144,256]
    launch_pdl(dim3(DIM / 64, M144 / 16, B_), dim3(128),
        u_softmax_gemm, na_b2, token_init);

    // 6. broadcast unique rows to the full [4,19200,256] output
    launch_pdl(dim3(W_ / 4, H_, B_), dim3(256),
        scatter_kernel, (float4*)out);
}